// round 11
// baseline (speedup 1.0000x reference)
#include <cuda_runtime.h>
#include <cuda_bf16.h>

#define N_NODES 100000
#define N_EDGES 6400000
#define F_IN 5
#define F_HID 5
#define F_OUT 10

#define SCAN_B 1024
#define N_SCAN_BLOCKS ((N_NODES + SCAN_B - 1) / SCAN_B)   // 98

// ---- device scratch (allocation-free) ----
__device__ __align__(16) float g_x8[N_NODES * 8];   // padded input features (32B rows)
__device__ __align__(16) float g_h8[N_NODES * 8];   // padded layer-1 activations
__device__ int g_cnt[N_NODES];                      // in-degree
__device__ int g_scan[N_NODES];                     // scan workspace
__device__ int g_bsum[N_SCAN_BLOCKS];               // block sums
__device__ int g_rowstart[N_NODES];                 // CSR row starts
__device__ int g_pos[N_NODES];                      // scatter cursors
__device__ int g_csr[N_EDGES];                      // dst-sorted src indices

__device__ __forceinline__ float fast_sigmoid(float x) {
    return 1.0f / (1.0f + __expf(-x));
}

// ---- 1. init: zero degree counters, write padded x ----
__global__ __launch_bounds__(256) void init_kernel(const float* __restrict__ x) {
    int i = blockIdx.x * blockDim.x + threadIdx.x;
    if (i >= N_NODES) return;
    g_cnt[i] = 0;
    const float* xr = x + (size_t)i * F_IN;
    *reinterpret_cast<float4*>(g_x8 + (size_t)i * 8) = make_float4(xr[0], xr[1], xr[2], xr[3]);
    g_x8[(size_t)i * 8 + 4] = xr[4];
}

// ---- 2. histogram of dst (4 edges / thread) ----
__global__ __launch_bounds__(256) void hist_kernel(const int* __restrict__ dst) {
    int t = blockIdx.x * blockDim.x + threadIdx.x;
    int e = t * 4;
    if (e >= N_EDGES) return;
    int4 d = *reinterpret_cast<const int4*>(dst + e);
    atomicAdd(&g_cnt[d.x], 1);
    atomicAdd(&g_cnt[d.y], 1);
    atomicAdd(&g_cnt[d.z], 1);
    atomicAdd(&g_cnt[d.w], 1);
}

// ---- 3a. per-block exclusive scan ----
__global__ __launch_bounds__(SCAN_B) void scan1_kernel() {
    __shared__ int sh[SCAN_B];
    int tid = threadIdx.x;
    int i = blockIdx.x * SCAN_B + tid;
    int v = (i < N_NODES) ? g_cnt[i] : 0;
    sh[tid] = v;
    __syncthreads();
#pragma unroll
    for (int off = 1; off < SCAN_B; off <<= 1) {
        int t = (tid >= off) ? sh[tid - off] : 0;
        __syncthreads();
        sh[tid] += t;
        __syncthreads();
    }
    int incl = sh[tid];
    if (i < N_NODES) g_scan[i] = incl - v;          // exclusive
    if (tid == SCAN_B - 1) g_bsum[blockIdx.x] = incl;
}

// ---- 3b. scan the block sums (tiny, serial) ----
__global__ void scan2_kernel() {
    if (threadIdx.x == 0 && blockIdx.x == 0) {
        int acc = 0;
        for (int b = 0; b < N_SCAN_BLOCKS; b++) {
            int t = g_bsum[b];
            g_bsum[b] = acc;
            acc += t;
        }
    }
}

// ---- 3c. add offsets; init row starts + cursors ----
__global__ __launch_bounds__(SCAN_B) void scan3_kernel() {
    int i = blockIdx.x * SCAN_B + threadIdx.x;
    if (i >= N_NODES) return;
    int r = g_scan[i] + g_bsum[blockIdx.x];
    g_rowstart[i] = r;
    g_pos[i] = r;
}

// ---- 4. scatter src into dst-sorted CSR (4 edges / thread) ----
__global__ __launch_bounds__(256) void scatter_kernel(const int* __restrict__ src,
                                                      const int* __restrict__ dst) {
    int t = blockIdx.x * blockDim.x + threadIdx.x;
    int e = t * 4;
    if (e >= N_EDGES) return;
    int4 s = *reinterpret_cast<const int4*>(src + e);
    int4 d = *reinterpret_cast<const int4*>(dst + e);
    g_csr[atomicAdd(&g_pos[d.x], 1)] = s.x;
    g_csr[atomicAdd(&g_pos[d.y], 1)] = s.y;
    g_csr[atomicAdd(&g_pos[d.z], 1)] = s.z;
    g_csr[atomicAdd(&g_pos[d.w], 1)] = s.w;
}

// ---- 5. fused SAGE layer: warp-per-node pull aggregation + GEMV + sigmoid ----
template <bool LAYER1>
__global__ __launch_bounds__(256) void sage_layer_kernel(const float* __restrict__ Ws,
                                                         const float* __restrict__ Wn,
                                                         const float* __restrict__ b,
                                                         float* __restrict__ out) {
    int v = (blockIdx.x * blockDim.x + threadIdx.x) >> 5;
    if (v >= N_NODES) return;
    int lane = threadIdx.x & 31;

    const float* feat = LAYER1 ? g_x8 : g_h8;
    int base = g_rowstart[v];
    int cnt  = g_cnt[v];

    float a0 = 0.f, a1 = 0.f, a2 = 0.f, a3 = 0.f, a4 = 0.f;
    for (int i = lane; i < cnt; i += 32) {
        int s = g_csr[base + i];
        const float4 f = *reinterpret_cast<const float4*>(feat + (size_t)s * 8);
        float f4 = feat[(size_t)s * 8 + 4];
        a0 += f.x; a1 += f.y; a2 += f.z; a3 += f.w; a4 += f4;
    }
#pragma unroll
    for (int off = 16; off > 0; off >>= 1) {
        a0 += __shfl_xor_sync(0xFFFFFFFFu, a0, off);
        a1 += __shfl_xor_sync(0xFFFFFFFFu, a1, off);
        a2 += __shfl_xor_sync(0xFFFFFFFFu, a2, off);
        a3 += __shfl_xor_sync(0xFFFFFFFFu, a3, off);
        a4 += __shfl_xor_sync(0xFFFFFFFFu, a4, off);
    }
    float inv = 1.0f / fmaxf((float)cnt, 1.0f);
    float av[5] = {a0 * inv, a1 * inv, a2 * inv, a3 * inv, a4 * inv};
    float xv[5];
#pragma unroll
    for (int f = 0; f < 5; f++) xv[f] = feat[(size_t)v * 8 + f];

    const int FO = LAYER1 ? F_HID : F_OUT;
    if (lane < FO) {
        float acc = b[lane];
#pragma unroll
        for (int f = 0; f < 5; f++) {
            acc = fmaf(xv[f], Ws[f * FO + lane], acc);
            acc = fmaf(av[f], Wn[f * FO + lane], acc);
        }
        acc = fast_sigmoid(acc);
        if (LAYER1)
            g_h8[(size_t)v * 8 + lane] = acc;
        else
            out[(size_t)v * F_OUT + lane] = acc;
    }
}

extern "C" void kernel_launch(void* const* d_in, const int* in_sizes, int n_in,
                              void* d_out, int out_size) {
    const float* x   = (const float*)d_in[0];
    const int*   src = (const int*)d_in[1];
    const int*   dst = (const int*)d_in[2];
    const float* Ws1 = (const float*)d_in[3];
    const float* Wn1 = (const float*)d_in[4];
    const float* b1  = (const float*)d_in[5];
    const float* Ws2 = (const float*)d_in[6];
    const float* Wn2 = (const float*)d_in[7];
    const float* b2  = (const float*)d_in[8];
    float* out = (float*)d_out;

    const int nb_nodes = (N_NODES + 255) / 256;
    const int nb_edges4 = (N_EDGES / 4 + 255) / 256;
    const int nb_warps = (N_NODES * 32 + 255) / 256;

    init_kernel<<<nb_nodes, 256>>>(x);
    hist_kernel<<<nb_edges4, 256>>>(dst);
    scan1_kernel<<<N_SCAN_BLOCKS, SCAN_B>>>();
    scan2_kernel<<<1, 32>>>();
    scan3_kernel<<<N_SCAN_BLOCKS, SCAN_B>>>();
    scatter_kernel<<<nb_edges4, 256>>>(src, dst);
    sage_layer_kernel<true><<<nb_warps, 256>>>(Ws1, Wn1, b1, nullptr);
    sage_layer_kernel<false><<<nb_warps, 256>>>(Ws2, Wn2, b2, out);
}

// round 12
// speedup vs baseline: 1.2732x; 1.2732x over previous
#include <cuda_runtime.h>
#include <cuda_bf16.h>

#define N_NODES 100000
#define N_EDGES 6400000
#define F_IN 5
#define F_HID 5
#define F_OUT 10

// Scratch: padded rows, 32B (1 L2 sector) per node.
// g_agg row layout: [a0,a1,a2,a3,a4,deg,unused,unused]
__device__ __align__(16) float g_x8[N_NODES * 8];
__device__ __align__(16) float g_h8[N_NODES * 8];
__device__ __align__(16) float g_agg[N_NODES * 8];

__device__ __forceinline__ void red_add_v4(float* addr, float a, float b, float c, float d) {
    asm volatile("red.global.add.v4.f32 [%0], {%1,%2,%3,%4};"
                 :: "l"(addr), "f"(a), "f"(b), "f"(c), "f"(d) : "memory");
}
__device__ __forceinline__ void red_add_v2(float* addr, float a, float b) {
    asm volatile("red.global.add.v2.f32 [%0], {%1,%2};"
                 :: "l"(addr), "f"(a), "f"(b) : "memory");
}

__device__ __forceinline__ float fast_sigmoid(float x) {
    return 1.0f / (1.0f + __expf(-x));
}

// ---- init: pad x into 32B rows, zero agg rows (incl. deg slot) ----
__global__ __launch_bounds__(256) void init_kernel(const float* __restrict__ x) {
    int i = blockIdx.x * blockDim.x + threadIdx.x;
    if (i >= N_NODES) return;
    const float* xr = x + (size_t)i * F_IN;
    *reinterpret_cast<float4*>(g_x8 + (size_t)i * 8) = make_float4(xr[0], xr[1], xr[2], xr[3]);
    g_x8[(size_t)i * 8 + 4] = xr[4];
    *reinterpret_cast<float4*>(g_agg + (size_t)i * 8)     = make_float4(0.f, 0.f, 0.f, 0.f);
    *reinterpret_cast<float4*>(g_agg + (size_t)i * 8 + 4) = make_float4(0.f, 0.f, 0.f, 0.f);
}

// ---- edge pass: gather src row, 2 RED instrs into dst row's single sector ----
// LAYER1 adds 1.0 to the deg slot; LAYER2 adds 0.0 (exact no-op, preserves deg).
template <bool LAYER1>
__global__ __launch_bounds__(256) void edge_kernel(const int* __restrict__ src,
                                                   const int* __restrict__ dst) {
    int t = blockIdx.x * blockDim.x + threadIdx.x;
    int e = t * 4;
    if (e >= N_EDGES) return;
    const int4 s4 = *reinterpret_cast<const int4*>(src + e);
    const int4 d4 = *reinterpret_cast<const int4*>(dst + e);
    const float* feat = LAYER1 ? g_x8 : g_h8;
    const float degc = LAYER1 ? 1.0f : 0.0f;

    int ss[4] = {s4.x, s4.y, s4.z, s4.w};
    int dd[4] = {d4.x, d4.y, d4.z, d4.w};
#pragma unroll
    for (int k = 0; k < 4; k++) {
        const float4 v = __ldg(reinterpret_cast<const float4*>(feat + (size_t)ss[k] * 8));
        const float v4 = __ldg(feat + (size_t)ss[k] * 8 + 4);
        float* ap = g_agg + (size_t)dd[k] * 8;
        red_add_v4(ap, v.x, v.y, v.z, v.w);
        red_add_v2(ap + 4, v4, degc);
    }
}

// ---- layer-1 epilogue: h = sigmoid(x@Ws1 + mean@Wn1 + b1); re-zero agg[0..4] ----
__global__ __launch_bounds__(256) void node1_kernel(const float* __restrict__ Ws,
                                                    const float* __restrict__ Wn,
                                                    const float* __restrict__ b) {
    int v = blockIdx.x * blockDim.x + threadIdx.x;
    if (v >= N_NODES) return;
    float* ar = g_agg + (size_t)v * 8;
    float deg = ar[5];
    float inv = 1.0f / fmaxf(deg, 1.0f);
    float xv[F_IN], av[F_IN];
#pragma unroll
    for (int f = 0; f < F_IN; f++) {
        xv[f] = g_x8[(size_t)v * 8 + f];
        av[f] = ar[f] * inv;
    }
#pragma unroll
    for (int j = 0; j < F_HID; j++) {
        float acc = b[j];
#pragma unroll
        for (int f = 0; f < F_IN; f++) {
            acc = fmaf(xv[f], Ws[f * F_HID + j], acc);
            acc = fmaf(av[f], Wn[f * F_HID + j], acc);
        }
        g_h8[(size_t)v * 8 + j] = fast_sigmoid(acc);
    }
    // reset feature slots for layer 2; PRESERVE deg in slot 5
    *reinterpret_cast<float4*>(ar) = make_float4(0.f, 0.f, 0.f, 0.f);
    ar[4] = 0.0f;
}

// ---- layer-2 epilogue ----
__global__ __launch_bounds__(256) void node2_kernel(const float* __restrict__ Ws,
                                                    const float* __restrict__ Wn,
                                                    const float* __restrict__ b,
                                                    float* __restrict__ out) {
    int v = blockIdx.x * blockDim.x + threadIdx.x;
    if (v >= N_NODES) return;
    const float* ar = g_agg + (size_t)v * 8;
    float inv = 1.0f / fmaxf(ar[5], 1.0f);
    float hv[F_HID], av[F_HID];
#pragma unroll
    for (int f = 0; f < F_HID; f++) {
        hv[f] = g_h8[(size_t)v * 8 + f];
        av[f] = ar[f] * inv;
    }
#pragma unroll
    for (int j = 0; j < F_OUT; j++) {
        float acc = b[j];
#pragma unroll
        for (int f = 0; f < F_HID; f++) {
            acc = fmaf(hv[f], Ws[f * F_OUT + j], acc);
            acc = fmaf(av[f], Wn[f * F_OUT + j], acc);
        }
        out[(size_t)v * F_OUT + j] = fast_sigmoid(acc);
    }
}

extern "C" void kernel_launch(void* const* d_in, const int* in_sizes, int n_in,
                              void* d_out, int out_size) {
    const float* x   = (const float*)d_in[0];
    const int*   src = (const int*)d_in[1];
    const int*   dst = (const int*)d_in[2];
    const float* Ws1 = (const float*)d_in[3];
    const float* Wn1 = (const float*)d_in[4];
    const float* b1  = (const float*)d_in[5];
    const float* Ws2 = (const float*)d_in[6];
    const float* Wn2 = (const float*)d_in[7];
    const float* b2  = (const float*)d_in[8];
    float* out = (float*)d_out;

    const int nb_nodes  = (N_NODES + 255) / 256;
    const int nb_edges4 = (N_EDGES / 4 + 255) / 256;

    init_kernel<<<nb_nodes, 256>>>(x);
    edge_kernel<true><<<nb_edges4, 256>>>(src, dst);
    node1_kernel<<<nb_nodes, 256>>>(Ws1, Wn1, b1);
    edge_kernel<false><<<nb_edges4, 256>>>(src, dst);
    node2_kernel<<<nb_nodes, 256>>>(Ws2, Wn2, b2, out);
}

// round 16
// speedup vs baseline: 1.9742x; 1.5506x over previous
#include <cuda_runtime.h>
#include <cuda_fp16.h>
#include <cuda_bf16.h>

#define N_NODES 100000
#define N_EDGES 6400000
#define F_IN 5
#define F_HID 5
#define F_OUT 10

// 16B rows: 8 f16 lanes per node.
// layer-1 source row: [x0,x1][x2,x3][x4,1.0][0,0]   (lane 5 = degree increment)
// layer-2 source row: [g0,g1][g2,g3][g4,0 ][0,0]    (g = h - 0.5, centered)
__device__ __align__(16) uint4 g_xpack[N_NODES];
__device__ __align__(16) uint4 g_hpack[N_NODES];
__device__ __align__(16) uint4 g_agg[N_NODES];
__device__ __align__(16) float g_h8[N_NODES * 8];   // full-precision h for self term
__device__ float g_deg[N_NODES];

__device__ __forceinline__ float fast_sigmoid(float x) {
    return 1.0f / (1.0f + __expf(-x));
}

// ONE 16-byte packed-half atomic per edge: 8 f16 lanes.
__device__ __forceinline__ void red_add_v4_f16x2(uint4* addr, uint4 v) {
    asm volatile("red.global.add.noftz.v4.f16x2 [%0], {%1,%2,%3,%4};"
                 :: "l"(addr), "r"(v.x), "r"(v.y), "r"(v.z), "r"(v.w) : "memory");
}

__device__ __forceinline__ unsigned pack_h2(float a, float b) {
    __half2 h = __floats2half2_rn(a, b);
    return *reinterpret_cast<unsigned*>(&h);
}
__device__ __forceinline__ float2 unpack_h2(unsigned u) {
    __half2 h = *reinterpret_cast<__half2*>(&u);
    return __half22float2(h);
}

// ---- init: encode x rows (f16), zero accumulators ----
__global__ __launch_bounds__(256) void init_kernel(const float* __restrict__ x) {
    int i = blockIdx.x * blockDim.x + threadIdx.x;
    if (i >= N_NODES) return;
    const float* xr = x + (size_t)i * F_IN;
    uint4 p;
    p.x = pack_h2(xr[0], xr[1]);
    p.y = pack_h2(xr[2], xr[3]);
    p.z = pack_h2(xr[4], 1.0f);     // lane5 = degree increment
    p.w = 0u;
    g_xpack[i] = p;
    g_agg[i] = make_uint4(0u, 0u, 0u, 0u);
}

// ---- edge pass: gather 16B source row, ONE v4.f16x2 RED into dst row ----
template <bool LAYER1>
__global__ __launch_bounds__(256) void edge_kernel(const int* __restrict__ src,
                                                   const int* __restrict__ dst) {
    int t = blockIdx.x * blockDim.x + threadIdx.x;
    int e = t * 4;
    if (e >= N_EDGES) return;
    const int4 s4 = *reinterpret_cast<const int4*>(src + e);
    const int4 d4 = *reinterpret_cast<const int4*>(dst + e);
    const uint4* tab = LAYER1 ? g_xpack : g_hpack;

    int ss[4] = {s4.x, s4.y, s4.z, s4.w};
    int dd[4] = {d4.x, d4.y, d4.z, d4.w};
#pragma unroll
    for (int k = 0; k < 4; k++) {
        uint4 v = __ldg(&tab[ss[k]]);
        red_add_v4_f16x2(&g_agg[dd[k]], v);
    }
}

// ---- layer-1 epilogue: decode f16 sums + exact deg, GEMV + sigmoid,
//      write full-precision h + centered f16 h row, reset agg ----
__global__ __launch_bounds__(256) void node1_kernel(const float* __restrict__ x,
                                                    const float* __restrict__ Ws,
                                                    const float* __restrict__ Wn,
                                                    const float* __restrict__ b) {
    int v = blockIdx.x * blockDim.x + threadIdx.x;
    if (v >= N_NODES) return;
    uint4 a = g_agg[v];
    float2 s01 = unpack_h2(a.x);
    float2 s23 = unpack_h2(a.y);
    float2 s4d = unpack_h2(a.z);
    float fdeg = s4d.y;                       // exact integer count in f16
    float inv = 1.0f / fmaxf(fdeg, 1.0f);

    float av[F_IN] = {s01.x * inv, s01.y * inv, s23.x * inv, s23.y * inv, s4d.x * inv};

    const float* xr = x + (size_t)v * F_IN;
    float xv[F_IN];
#pragma unroll
    for (int f = 0; f < F_IN; f++) xv[f] = __ldg(xr + f);

    float h[F_HID];
#pragma unroll
    for (int j = 0; j < F_HID; j++) {
        float acc = b[j];
#pragma unroll
        for (int f = 0; f < F_IN; f++) {
            acc = fmaf(xv[f], Ws[f * F_HID + j], acc);
            acc = fmaf(av[f], Wn[f * F_HID + j], acc);
        }
        h[j] = fast_sigmoid(acc);
    }
    // full-precision h for the self term
    *reinterpret_cast<float4*>(g_h8 + (size_t)v * 8) = make_float4(h[0], h[1], h[2], h[3]);
    g_h8[(size_t)v * 8 + 4] = h[4];
    // centered f16 row for layer-2 aggregation (g = h - 0.5 keeps sums zero-mean)
    uint4 p;
    p.x = pack_h2(h[0] - 0.5f, h[1] - 0.5f);
    p.y = pack_h2(h[2] - 0.5f, h[3] - 0.5f);
    p.z = pack_h2(h[4] - 0.5f, 0.0f);
    p.w = 0u;
    g_hpack[v] = p;
    g_deg[v] = fdeg;
    g_agg[v] = make_uint4(0u, 0u, 0u, 0u);    // reset for layer 2
}

// ---- layer-2 epilogue: mean(h) = sum(g)/deg + 0.5 ----
__global__ __launch_bounds__(256) void node2_kernel(const float* __restrict__ Ws,
                                                    const float* __restrict__ Wn,
                                                    const float* __restrict__ b,
                                                    float* __restrict__ out) {
    int v = blockIdx.x * blockDim.x + threadIdx.x;
    if (v >= N_NODES) return;
    uint4 a = g_agg[v];
    float2 s01 = unpack_h2(a.x);
    float2 s23 = unpack_h2(a.y);
    float2 s4_ = unpack_h2(a.z);
    float fdeg = g_deg[v];
    float inv = 1.0f / fmaxf(fdeg, 1.0f);
    float bias = (fdeg > 0.0f) ? 0.5f : 0.0f;   // isolated nodes: mean = 0

    float av[F_HID];
    av[0] = s01.x * inv + bias;
    av[1] = s01.y * inv + bias;
    av[2] = s23.x * inv + bias;
    av[3] = s23.y * inv + bias;
    av[4] = s4_.x * inv + bias;

    float hv[F_HID];
#pragma unroll
    for (int f = 0; f < F_HID; f++) hv[f] = g_h8[(size_t)v * 8 + f];

#pragma unroll
    for (int j = 0; j < F_OUT; j++) {
        float acc = b[j];
#pragma unroll
        for (int f = 0; f < F_HID; f++) {
            acc = fmaf(hv[f], Ws[f * F_OUT + j], acc);
            acc = fmaf(av[f], Wn[f * F_OUT + j], acc);
        }
        out[(size_t)v * F_OUT + j] = fast_sigmoid(acc);
    }
}

extern "C" void kernel_launch(void* const* d_in, const int* in_sizes, int n_in,
                              void* d_out, int out_size) {
    const float* x   = (const float*)d_in[0];
    const int*   src = (const int*)d_in[1];
    const int*   dst = (const int*)d_in[2];
    const float* Ws1 = (const float*)d_in[3];
    const float* Wn1 = (const float*)d_in[4];
    const float* b1  = (const float*)d_in[5];
    const float* Ws2 = (const float*)d_in[6];
    const float* Wn2 = (const float*)d_in[7];
    const float* b2  = (const float*)d_in[8];
    float* out = (float*)d_out;

    const int nb_nodes  = (N_NODES + 255) / 256;
    const int nb_edges4 = (N_EDGES / 4 + 255) / 256;

    init_kernel<<<nb_nodes, 256>>>(x);
    edge_kernel<true><<<nb_edges4, 256>>>(src, dst);
    node1_kernel<<<nb_nodes, 256>>>(x, Ws1, Wn1, b1);
    edge_kernel<false><<<nb_edges4, 256>>>(src, dst);
    node2_kernel<<<nb_nodes, 256>>>(Ws2, Wn2, b2, out);
}